// round 6
// baseline (speedup 1.0000x reference)
#include <cuda_runtime.h>

// GwcVolume: group-wise correlation cost volumes (lr + rl).
// Shapes (fixed): B=1, F=320, H=128, W=256, G=40, C=8, D=48.
//
// lr[g,d,h,w]  = (w>=d)   * (1/C) * sum_c L[gC+c,h,w] * R[gC+c,h,w-d]
// rl[g,d,h,w'] = (w'<W-d) * lr[g,d,h,w'+d]     (same values, shifted)
//
// One block per (g,h) row; 64 threads, each owning 4 consecutive w.
// R row staged in smem with [c][w%4][w/4] layout (conflict-free stride-4
// gathers). Per-thread register sliding window over R: when bins step by +1
// (the actual input: arange), each bin needs only ONE new smem float per
// channel — 4x fewer smem bytes than the naive gather. Falls back to a full
// window reload for non-unit bin steps. lr stored as aligned STG.128; rl
// scattered via wrap index (w-d)&255 which also places the zero tails
// branchlessly. Every output element written exactly once.

constexpr int H = 128;
constexpr int W = 256;
constexpr int G = 40;
constexpr int C = 8;
constexpr int D = 48;
constexpr int V = 4;          // outputs per thread
constexpr int T = W / V;      // 64 threads per block

__global__ __launch_bounds__(T, 16)
void gwc_volume_kernel(const float* __restrict__ L,
                       const float* __restrict__ R,
                       const int*   __restrict__ bins,
                       float*       __restrict__ out)
{
    const int h = blockIdx.x;     // 0..H-1
    const int g = blockIdx.y;     // 0..G-1
    const int t = threadIdx.x;    // 0..T-1
    const int w0 = 4 * t;         // first w owned by this thread

    __shared__ float Rsh[C][4][T];   // [c][w%4][w/4] : 8 KB
    __shared__ int   dsh[D];

    const long HW   = (long)H * W;
    const long base = (long)g * C * HW + (long)h * W + w0;

    // Stage: L quad -> registers, R quad -> smem (r-major layout).
    float Lh[C][V];
#pragma unroll
    for (int c = 0; c < C; ++c) {
        const float4 lv = __ldg((const float4*)(L + base + (long)c * HW));
        Lh[c][0] = lv.x; Lh[c][1] = lv.y; Lh[c][2] = lv.z; Lh[c][3] = lv.w;
        const float4 rv = __ldg((const float4*)(R + base + (long)c * HW));
        Rsh[c][0][t] = rv.x;
        Rsh[c][1][t] = rv.y;
        Rsh[c][2][t] = rv.z;
        Rsh[c][3][t] = rv.w;
    }
    if (t < D) dsh[t] = bins[t];
    __syncthreads();

    float* __restrict__ lrp = out + (long)g * D * HW + (long)h * W;
    float* __restrict__ rlp = lrp + (long)G * D * HW;

    // Circular register window: logical win[j] (= R[c][(w0+j-d)&255]) lives in
    // slot[(j - i) & 3], so with the bin loop unrolled by 4 all slot indices
    // are compile-time constants (no register-shuffle MOVs).
    float win[C][4];
    int dprev = -2;   // forces a full reload on the first bin

    const float* RshF = &Rsh[0][0][0];   // flat view: c*256 + r*64 + q

#pragma unroll 1
    for (int i0 = 0; i0 < D; i0 += 4) {
#pragma unroll
        for (int p = 0; p < 4; ++p) {
            const int i    = i0 + p;
            const int d    = dsh[i];
            const int idx0 = (w0 - d) & (W - 1);   // position of win[0] in the row

            if (d == dprev + 1) {
                // Slide by one: fetch only the new leading element.
                const int r = idx0 & 3, q = idx0 >> 2;   // r uniform across lanes
#pragma unroll
                for (int c = 0; c < C; ++c)
                    win[c][(0 - p) & 3] = RshF[c * 256 + r * 64 + q];
            } else {
                // General step: reload the whole window (never taken for arange bins).
#pragma unroll
                for (int j = 0; j < 4; ++j) {
                    const int ii = (idx0 + j) & (W - 1);
                    const int r = ii & 3, q = ii >> 2;
#pragma unroll
                    for (int c = 0; c < C; ++c)
                        win[c][(j - p) & 3] = RshF[c * 256 + r * 64 + q];
                }
            }
            dprev = d;

            // Four dot products over C=8 channels.
            float v[4];
#pragma unroll
            for (int j = 0; j < 4; ++j) {
                float acc = Lh[0][j] * win[0][(j - p) & 3];
#pragma unroll
                for (int c = 1; c < C; ++c)
                    acc = fmaf(Lh[c][j], win[c][(j - p) & 3], acc);
                // zero-fill: lr for w<d, and (via wrap scatter) rl tail [W-d, W)
                v[j] = (w0 + j >= d) ? acc * (1.0f / (float)C) : 0.0f;
            }

            const long off = (long)i * HW;
            __stcs((float4*)(lrp + off + w0),
                   make_float4(v[0], v[1], v[2], v[3]));        // lr[g,i,h,w0..w0+3]
#pragma unroll
            for (int j = 0; j < 4; ++j)
                __stcs(rlp + off + ((idx0 + j) & (W - 1)), v[j]); // rl[g,i,h,(w-d) mod W]
        }
    }
}

extern "C" void kernel_launch(void* const* d_in, const int* in_sizes, int n_in,
                              void* d_out, int out_size)
{
    const float* Lf   = (const float*)d_in[0];   // features_left  [1,320,128,256] f32
    const float* Rf   = (const float*)d_in[1];   // features_right [1,320,128,256] f32
    const int*   bins = (const int*)  d_in[2];   // [48] int32

    dim3 grid(H, G);
    gwc_volume_kernel<<<grid, T>>>(Lf, Rf, bins, (float*)d_out);
}

// round 7
// speedup vs baseline: 2.6314x; 2.6314x over previous
#include <cuda_runtime.h>

// GwcVolume: group-wise correlation cost volumes (lr + rl).
// Shapes (fixed): B=1, F=320, H=128, W=256, G=40, C=8, D=48.
//
// lr[g,d,h,w]  = (w>=d)   * (1/C) * sum_c L[gC+c,h,w] * R[gC+c,h,w-d]
// rl[g,d,h,w'] = (w'<W-d) * lr[g,d,h,w'+d]     (same values, shifted)
//
// One block per (g,h) row; 128 threads, each owning w0=2t, w0+1.
// Bins processed in packs of P=8 consecutive disparities: the R-window
// R[w0-d0-7 .. w0-d0+1] (9 floats, fetched as 5 aligned conflict-free LDS.64)
// serves all 16 dot products of the pack -> 25% fewer L1 wavefronts than the
// per-bin gather. All iterations independent (full ILP, no carried deps).
// Shared-value trick: each dot product stored to lr (aligned STG.64) and to
// rl at the wrap index (w-d)&255, which also places the zero tails of both
// volumes branchlessly. Scalar fallback path for non-arange bins.

constexpr int H = 128;
constexpr int W = 256;
constexpr int G = 40;
constexpr int C = 8;
constexpr int D = 48;
constexpr int T = 128;        // threads per block (V=2 outputs each)
constexpr int P = 8;          // bins per pack

__global__ __launch_bounds__(T, 6)
void gwc_volume_kernel(const float* __restrict__ L,
                       const float* __restrict__ R,
                       const int*   __restrict__ bins,
                       float*       __restrict__ out)
{
    const int h  = blockIdx.x;    // 0..H-1
    const int g  = blockIdx.y;    // 0..G-1
    const int t  = threadIdx.x;   // 0..T-1
    const int w0 = 2 * t;

    __shared__ __align__(16) float Rsh[C][W];   // 8 KB
    __shared__ int dsh[D];

    const long HW   = (long)H * W;
    const long base = (long)g * C * HW + (long)h * W + w0;

    // Stage inputs (coalesced LDG.64; each input byte read from DRAM once).
    // Fold 1/C into L: scaling by 0.125 is exact, result bitwise identical.
    float Lh[C][2];
#pragma unroll
    for (int c = 0; c < C; ++c) {
        const float2 lv = *(const float2*)(L + base + (long)c * HW);
        Lh[c][0] = lv.x * 0.125f;
        Lh[c][1] = lv.y * 0.125f;
        *(float2*)&Rsh[c][w0] = *(const float2*)(R + base + (long)c * HW);
    }
    if (t < D) dsh[t] = bins[t];
    __syncthreads();

    const float* __restrict__ RshF = &Rsh[0][0];
    float* __restrict__ lrq = out + (long)g * D * HW + (long)h * W;
    float* __restrict__ rlq = lrq + (long)G * D * HW;

#pragma unroll 1
    for (int i0 = 0; i0 < D; i0 += P, lrq += P * HW, rlq += P * HW) {
        const int d0 = dsh[i0];
        bool fast = ((d0 & 1) == 0);
#pragma unroll
        for (int p = 1; p < P; ++p) fast = fast && (dsh[i0 + p] == d0 + p);

        if (fast) {
            const int m = (w0 - d0) & (W - 1);   // even

            float v[P][2];
#pragma unroll
            for (int p = 0; p < P; ++p) { v[p][0] = 0.f; v[p][1] = 0.f; }

#pragma unroll
            for (int c = 0; c < C; ++c) {
                // Window r[0..9] = R[c][m-8 .. m+1] (wrapped). Wrapped entries
                // feed only masked-to-zero outputs (w < d).
                float r[10];
#pragma unroll
                for (int k = 0; k < 5; ++k) {
                    const float2 f =
                        *(const float2*)&RshF[c * W + ((m - 8 + 2 * k) & (W - 1))];
                    r[2 * k]     = f.x;
                    r[2 * k + 1] = f.y;
                }
#pragma unroll
                for (int p = 0; p < P; ++p) {
                    v[p][0] = fmaf(Lh[c][0], r[8 - p], v[p][0]);
                    v[p][1] = fmaf(Lh[c][1], r[9 - p], v[p][1]);
                }
            }

#pragma unroll
            for (int p = 0; p < P; ++p) {
                const int d = d0 + p;
                const float a = (w0     >= d) ? v[p][0] : 0.f;
                const float b = (w0 + 1 >= d) ? v[p][1] : 0.f;

                __stcs((float2*)(lrq + (long)p * HW + w0), make_float2(a, b));

                const int pos = (m - p) & (W - 1);   // rl position of 'a'
                if ((p & 1) == 0) {                  // pos even -> aligned pair
                    __stcs((float2*)(rlq + (long)p * HW + pos), make_float2(a, b));
                } else {
                    __stcs(rlq + (long)p * HW + pos, a);
                    __stcs(rlq + (long)p * HW + ((pos + 1) & (W - 1)), b);
                }
            }
        } else {
            // General bins: per-bin scalar path (R4 semantics).
#pragma unroll 1
            for (int q = 0; q < P; ++q) {
                const int d  = dsh[i0 + q];
                const int ia = (w0 - d) & (W - 1);
                const int ib = (w0 + 1 - d) & (W - 1);
                float a = 0.f, b = 0.f;
#pragma unroll
                for (int c = 0; c < C; ++c) {
                    a = fmaf(Lh[c][0], RshF[c * W + ia], a);
                    b = fmaf(Lh[c][1], RshF[c * W + ib], b);
                }
                a = (w0     >= d) ? a : 0.f;
                b = (w0 + 1 >= d) ? b : 0.f;
                const long off = (long)q * HW;
                __stcs(lrq + off + w0,     a);
                __stcs(lrq + off + w0 + 1, b);
                __stcs(rlq + off + ia, a);
                __stcs(rlq + off + ib, b);
            }
        }
    }
}

extern "C" void kernel_launch(void* const* d_in, const int* in_sizes, int n_in,
                              void* d_out, int out_size)
{
    const float* Lf   = (const float*)d_in[0];   // features_left  [1,320,128,256] f32
    const float* Rf   = (const float*)d_in[1];   // features_right [1,320,128,256] f32
    const int*   bins = (const int*)  d_in[2];   // [48] int32

    dim3 grid(H, G);
    gwc_volume_kernel<<<grid, T>>>(Lf, Rf, bins, (float*)d_out);
}